// round 15
// baseline (speedup 1.0000x reference)
#include <cuda_runtime.h>
#include <math.h>

#define TB 16
#define TS 256

// ---------------- device scratch ----------------
__device__ float g_h1[8*16*64*64];
__device__ float g_part[128*32];
__device__ float g_te[64];
__device__ float g_Wupd[2304];              // [co][ci][pos]
__device__ float g_Wtau[256];               // [co][ci]
__device__ float g_T9[9*33*17];             // [pos][code(33:32=zero)][c] stride-17
__device__ float g_Acb[32*17];              // beta*code
__device__ float g_OMB[32*17];              // 1-beta
__device__ float g_cbsq[32];
__device__ float g_declut[32];
__device__ unsigned char g_idxA[TB*TS*TS];
__device__ unsigned char g_idxB[TB*TS*TS];

// ---------------- encoder conv1 ----------------
__global__ __launch_bounds__(256) void k_enc1(const float* __restrict__ din,
                                              const float* __restrict__ dmo,
                                              const float* __restrict__ w1,
                                              const float* __restrict__ b1)
{
    __shared__ float sw[288];
    __shared__ float sb[16];
    int t = threadIdx.x;
    for (int i = t; i < 288; i += 256) sw[i] = w1[i];
    if (t < 16) sb[t] = b1[t];
    __syncthreads();
    int idx = blockIdx.x * 256 + t;
    int b = idx >> 12, p = idx & 4095, y = p >> 6, x = p & 63;
    const float* i0 = din + b * 4096;
    const float* i1 = dmo + b * 4096;
    float acc[16];
#pragma unroll
    for (int c = 0; c < 16; c++) acc[c] = sb[c];
#pragma unroll
    for (int ky = 0; ky < 3; ky++) {
        int yy = y + ky - 1;
        if ((unsigned)yy >= 64u) continue;
#pragma unroll
        for (int kx = 0; kx < 3; kx++) {
            int xx = x + kx - 1;
            if ((unsigned)xx >= 64u) continue;
            float v0 = i0[yy*64+xx], v1 = i1[yy*64+xx];
            int pos = ky*3+kx;
#pragma unroll
            for (int c = 0; c < 16; c++)
                acc[c] = fmaf(sw[c*18+pos], v0, fmaf(sw[c*18+9+pos], v1, acc[c]));
        }
    }
#pragma unroll
    for (int c = 0; c < 16; c++)
        g_h1[((b*16+c) << 12) + p] = fmaxf(acc[c], 0.f);
}

// ---------------- encoder conv2 + relu + spatial sum ----------------
__global__ __launch_bounds__(256) void k_enc2(const float* __restrict__ w2,
                                              const float* __restrict__ b2)
{
    __shared__ float sh[16][6][66];
    __shared__ float sw[32][145];
    __shared__ float spart[8][32];
    int tx = threadIdx.x, ty = threadIdx.y;
    int t = ty * 32 + tx;
    int band = blockIdx.x, b = blockIdx.y;
    float* swf = &sw[0][0];
    for (int i = t; i < 4608; i += 256) { int oc = i/144, j = i%144; swf[oc*145+j] = w2[i]; }
    int r0 = band * 4;
    for (int i = t; i < 16*6*66; i += 256) {
        int ci = i / 396; int rem = i % 396; int r = rem / 66; int xx = rem % 66;
        int gy = r0 + r - 1; int gx = xx - 1;
        float v = 0.f;
        if ((unsigned)gy < 64u && (unsigned)gx < 64u)
            v = g_h1[((b*16+ci) << 12) + gy*64 + gx];
        sh[ci][r][xx] = v;
    }
    __syncthreads();
    int oc = tx;
    float bias = b2[oc];
    float tsum = 0.f;
    for (int p = ty; p < 256; p += 8) {
        int r = p >> 6; int x = p & 63;
        float acc = bias;
#pragma unroll
        for (int ky = 0; ky < 3; ky++) {
#pragma unroll
            for (int kx = 0; kx < 3; kx++) {
                int pos = ky*3+kx;
#pragma unroll
                for (int ci = 0; ci < 16; ci++)
                    acc = fmaf(sh[ci][r+ky][x+kx], swf[oc*145 + ci*9 + pos], acc);
            }
        }
        tsum += fmaxf(acc, 0.f);
    }
    spart[ty][oc] = tsum;
    __syncthreads();
    if (ty == 0) {
        float s = 0.f;
#pragma unroll
        for (int k = 0; k < 8; k++) s += spart[k][oc];
        g_part[(b*16+band)*32 + oc] = s;
    }
}

// ---------------- slim tiny stage: te, tau hypernet, tau tables ----------------
__global__ __launch_bounds__(256) void k_small(
    const float* __restrict__ enc_lw, const float* __restrict__ enc_lb,
    const float* __restrict__ gt_w1, const float* __restrict__ gt_b1,
    const float* __restrict__ gt_w2, const float* __restrict__ gt_b2,
    const float* __restrict__ cb, const float* __restrict__ dec_w,
    const float* __restrict__ dec_b)
{
    __shared__ float s_hbar[32];
    __shared__ float s_te[64];
    __shared__ float s_ht[64];
    __shared__ float s_cb[512];
    int t = threadIdx.x;
    if (t < 32) {
        float s = 0.f;
        for (int i = 0; i < 128; i++) s += g_part[i*32 + t];
        s_hbar[t] = s * (1.f/(8.f*4096.f));
    }
    for (int i = t; i < 512; i += 256) s_cb[i] = cb[i];
    __syncthreads();
    if (t < 64) {
        float a = enc_lb[t];
        for (int f = 0; f < 32; f++) a = fmaf(enc_lw[t*32+f], s_hbar[f], a);
        s_te[t] = a;
        g_te[t] = a;
    }
    __syncthreads();
    if (t < 64) {
        float a = gt_b1[t];
        for (int e = 0; e < 64; e++) a = fmaf(gt_w1[t*64+e], s_te[e], a);
        s_ht[t] = fmaxf(a, 0.f);
    }
    __syncthreads();
    for (int o = t; o < 256; o += 256) {
        float a = gt_b2[o];
        for (int i = 0; i < 64; i++) a = fmaf(gt_w2[o*64+i], s_ht[i], a);
        g_Wtau[o] = a;
    }
    __syncthreads();
    for (int o = t; o < 512; o += 256) {
        int k = o >> 4, c = o & 15;
        float a = 0.f;
        for (int ci = 0; ci < 16; ci++) a = fmaf(g_Wtau[c*16+ci], s_cb[k*16+ci], a);
        float beta = 1.f / (1.f + __expf(-a));
        g_Acb[k*17+c] = beta * s_cb[k*16+c];
        g_OMB[k*17+c] = 1.f - beta;
    }
    if (t < 32) {
        float sq = 0.f, dv = dec_b[0];
        for (int c = 0; c < 16; c++) {
            float cc = s_cb[t*16+c];
            sq = fmaf(cc, cc, sq);
            dv = fmaf(dec_w[c], cc, dv);
        }
        g_cbsq[t] = sq;
        g_declut[t] = 1.f / (1.f + __expf(-dv));
    }
}

// ---------------- parallel table gen: one block per co ----------------
__global__ __launch_bounds__(256) void k_tables(
    const float* __restrict__ gu_w1, const float* __restrict__ gu_b1,
    const float* __restrict__ gu_w2, const float* __restrict__ gu_b2,
    const float* __restrict__ cb)
{
    __shared__ float s_hu[128];
    __shared__ float s_w[144];     // this co's Wupd slice [ci*9+pos]
    __shared__ float s_cb[512];
    int t = threadIdx.x;
    int co = blockIdx.x;
    for (int i = t; i < 512; i += 256) s_cb[i] = cb[i];
    if (t < 128) {
        float a = gu_b1[t];
        for (int e = 0; e < 64; e++) a = fmaf(gu_w1[t*64+e], g_te[e], a);
        s_hu[t] = fmaxf(a, 0.f);
    }
    __syncthreads();
    for (int i = t; i < 144; i += 256) {
        int o = co*144 + i;        // o = (co*16+ci)*9+pos, i = ci*9+pos
        float a = gu_b2[o];
        for (int j = 0; j < 128; j++) a = fmaf(gu_w2[o*128+j], s_hu[j], a);
        g_Wupd[o] = a;
        s_w[i] = a;
    }
    __syncthreads();
    for (int i = t; i < 297; i += 256) {
        int pos = i / 33, k = i % 33;
        float v = 0.f;
        if (k < 32) {
            for (int ci = 0; ci < 16; ci++)
                v = fmaf(s_w[ci*9+pos], s_cb[k*16+ci], v);
        }
        g_T9[(pos*33+k)*17 + co] = v;
    }
}

// ---------------- fused stem + step 1: co-split conv (4px x 4co per thread) ----------------
// dyn smem layout (float offsets):
//   s_t  float4[4*10*34] @0      (5440 floats)
//   sin_ [12*36]          @5440  (432)
//   s_sw [144]            @5872
//   s_sb [16]             @6016
//   s_W  [2304]           @6032  [pos][ci][co]
//   s_Wt [256]            @8336  [ci][co]
//   s_cb [512]            @8592
//   s_cq [32]             @9104
//   s_d  [256*20]         @9136  (5120) raw conv sums, stride-20 pad
#define S1F_FLOATS 14256
#define S1F_BYTES (S1F_FLOATS*4)

__global__ __launch_bounds__(256, 2) void k_step1f(const float* __restrict__ tin,
                                                   const float* __restrict__ stw,
                                                   const float* __restrict__ stb,
                                                   const float* __restrict__ cb)
{
    extern __shared__ float sm[];
    float4* s_t  = (float4*)sm;
    float*  sin_ = sm + 5440;
    float*  s_sw = sm + 5872;
    float*  s_sb = sm + 6016;
    float*  s_W  = sm + 6032;
    float*  s_Wt = sm + 8336;
    float*  s_cb = sm + 8592;
    float*  s_cq = sm + 9104;
    float*  s_d  = sm + 9136;

    int tx = threadIdx.x, ty = threadIdx.y, t = ty*32+tx;
    for (int i = t; i < 144; i += 256) { int co = i/9, pos = i%9; s_sw[pos*16+co] = stw[i]; }
    if (t < 16) s_sb[t] = stb[t];
    for (int i = t; i < 2304; i += 256) {
        int co = i & 15, ci = (i >> 4) & 15, pos = i >> 8;
        s_W[i] = g_Wupd[(co*16+ci)*9 + pos];
    }
    for (int i = t; i < 256; i += 256) { int co = i & 15, ci = i >> 4; s_Wt[i] = g_Wtau[co*16+ci]; }
    for (int i = t; i < 512; i += 256) s_cb[i] = cb[i];
    if (t < 32) s_cq[t] = g_cbsq[t];
    int X0 = blockIdx.x*32, Y0 = blockIdx.y*8, b = blockIdx.z;
    const float* img = tin + (size_t)b*65536;
    for (int i = t; i < 432; i += 256) {
        int rr = i/36, cc = i%36;
        int gy = Y0-2+rr, gx = X0-2+cc;
        float v = 0.f;
        if ((unsigned)gy < 256u && (unsigned)gx < 256u) v = img[gy*256+gx];
        sin_[i] = v;
    }
    __syncthreads();
    // stem over 10x34 halo region (zero outside image bounds)
    for (int i = t; i < 340; i += 256) {
        int r = i/34, c = i%34;
        int gy = Y0+r-1, gx = X0+c-1;
        float4 o0 = make_float4(0,0,0,0), o1 = o0, o2 = o0, o3 = o0;
        if ((unsigned)gy < 256u && (unsigned)gx < 256u) {
            float acc[16];
#pragma unroll
            for (int cc = 0; cc < 16; cc++) acc[cc] = s_sb[cc];
#pragma unroll
            for (int pos = 0; pos < 9; pos++) {
                float v = sin_[(r + pos/3)*36 + (c + pos%3)];
                const float4* w4 = (const float4*)&s_sw[pos*16];
#pragma unroll
                for (int g = 0; g < 4; g++) {
                    float4 wv = w4[g];
                    acc[g*4+0] = fmaf(wv.x, v, acc[g*4+0]);
                    acc[g*4+1] = fmaf(wv.y, v, acc[g*4+1]);
                    acc[g*4+2] = fmaf(wv.z, v, acc[g*4+2]);
                    acc[g*4+3] = fmaf(wv.w, v, acc[g*4+3]);
                }
            }
            o0 = make_float4(fmaxf(acc[0],0.f),fmaxf(acc[1],0.f),fmaxf(acc[2],0.f),fmaxf(acc[3],0.f));
            o1 = make_float4(fmaxf(acc[4],0.f),fmaxf(acc[5],0.f),fmaxf(acc[6],0.f),fmaxf(acc[7],0.f));
            o2 = make_float4(fmaxf(acc[8],0.f),fmaxf(acc[9],0.f),fmaxf(acc[10],0.f),fmaxf(acc[11],0.f));
            o3 = make_float4(fmaxf(acc[12],0.f),fmaxf(acc[13],0.f),fmaxf(acc[14],0.f),fmaxf(acc[15],0.f));
        }
        s_t[(0*10+r)*34+c] = o0;
        s_t[(1*10+r)*34+c] = o1;
        s_t[(2*10+r)*34+c] = o2;
        s_t[(3*10+r)*34+c] = o3;
    }
    __syncthreads();

    // co-split conv: thread = (slot, cog); slot -> x=slot&31, y0=slot>>5;
    {
        int slot = t >> 2, cog = t & 3;
        int cx = slot & 31, cy0 = slot >> 5;
        float4 acc0 = make_float4(0,0,0,0), acc1 = acc0, acc2 = acc0, acc3 = acc0;
#pragma unroll
        for (int pos = 0; pos < 9; pos++) {
            int dy = pos/3, dx = pos%3;
#pragma unroll
            for (int q = 0; q < 4; q++) {
                float4 v0 = s_t[(q*10 + cy0 + 0 + dy)*34 + cx + dx];
                float4 v1 = s_t[(q*10 + cy0 + 2 + dy)*34 + cx + dx];
                float4 v2 = s_t[(q*10 + cy0 + 4 + dy)*34 + cx + dx];
                float4 v3 = s_t[(q*10 + cy0 + 6 + dy)*34 + cx + dx];
                float c0[4] = {v0.x, v0.y, v0.z, v0.w};
                float c1[4] = {v1.x, v1.y, v1.z, v1.w};
                float c2[4] = {v2.x, v2.y, v2.z, v2.w};
                float c3[4] = {v3.x, v3.y, v3.z, v3.w};
#pragma unroll
                for (int u = 0; u < 4; u++) {
                    float4 w = *(const float4*)&s_W[(pos*16 + q*4 + u)*16 + cog*4];
                    float s0 = c0[u], s1 = c1[u], s2 = c2[u], s3 = c3[u];
                    acc0.x = fmaf(w.x, s0, acc0.x); acc0.y = fmaf(w.y, s0, acc0.y);
                    acc0.z = fmaf(w.z, s0, acc0.z); acc0.w = fmaf(w.w, s0, acc0.w);
                    acc1.x = fmaf(w.x, s1, acc1.x); acc1.y = fmaf(w.y, s1, acc1.y);
                    acc1.z = fmaf(w.z, s1, acc1.z); acc1.w = fmaf(w.w, s1, acc1.w);
                    acc2.x = fmaf(w.x, s2, acc2.x); acc2.y = fmaf(w.y, s2, acc2.y);
                    acc2.z = fmaf(w.z, s2, acc2.z); acc2.w = fmaf(w.w, s2, acc2.w);
                    acc3.x = fmaf(w.x, s3, acc3.x); acc3.y = fmaf(w.y, s3, acc3.y);
                    acc3.z = fmaf(w.z, s3, acc3.z); acc3.w = fmaf(w.w, s3, acc3.w);
                }
            }
        }
        *(float4*)&s_d[(slot +   0)*20 + cog*4] = acc0;
        *(float4*)&s_d[(slot +  64)*20 + cog*4] = acc1;
        *(float4*)&s_d[(slot + 128)*20 + cog*4] = acc2;
        *(float4*)&s_d[(slot + 192)*20 + cog*4] = acc3;
    }
    __syncthreads();

    // post-processing: 1 px per thread (px = t)
    {
        int x = t & 31, y = t >> 5;
        float acc[16];
#pragma unroll
        for (int g = 0; g < 4; g++) {
            float4 a = *(const float4*)&s_d[t*20 + g*4];
            acc[g*4+0] = a.x; acc[g*4+1] = a.y; acc[g*4+2] = a.z; acc[g*4+3] = a.w;
        }
        float zc[16];
#pragma unroll
        for (int q = 0; q < 4; q++) {
            float4 v = s_t[(q*10 + y+1)*34 + x+1];
            zc[q*4+0] = v.x; zc[q*4+1] = v.y; zc[q*4+2] = v.z; zc[q*4+3] = v.w;
        }
        float ta[16];
#pragma unroll
        for (int c = 0; c < 16; c++) ta[c] = 0.f;
#pragma unroll
        for (int ci = 0; ci < 16; ci++) {
            float s = zc[ci];
            const float4* w4 = (const float4*)&s_Wt[ci*16];
#pragma unroll
            for (int g = 0; g < 4; g++) {
                float4 wv = w4[g];
                ta[g*4+0] = fmaf(wv.x, s, ta[g*4+0]);
                ta[g*4+1] = fmaf(wv.y, s, ta[g*4+1]);
                ta[g*4+2] = fmaf(wv.z, s, ta[g*4+2]);
                ta[g*4+3] = fmaf(wv.w, s, ta[g*4+3]);
            }
        }
        float z[16];
#pragma unroll
        for (int c = 0; c < 16; c++) {
            float beta = 1.f / (1.f + __expf(-ta[c]));
            float delta = fmaxf(acc[c], 0.f);
            z[c] = fmaf(beta, zc[c] - delta, delta);
        }
        float best = 3.4e38f; int bi = 0;
#pragma unroll
        for (int k = 0; k < 32; k++) {
            const float4* c4 = (const float4*)&s_cb[k*16];
            float dot = 0.f;
#pragma unroll
            for (int g = 0; g < 4; g++) {
                float4 cv = c4[g];
                dot = fmaf(cv.x, z[g*4+0], dot);
                dot = fmaf(cv.y, z[g*4+1], dot);
                dot = fmaf(cv.z, z[g*4+2], dot);
                dot = fmaf(cv.w, z[g*4+3], dot);
            }
            float d = s_cq[k] - 2.f*dot;
            if (d < best) { best = d; bi = k; }
        }
        g_idxA[(b << 16) + (Y0+y)*256 + (X0+x)] = (unsigned char)bi;
    }
}

// ---------------- quantized step: 128x8 tile, 4 px/thread, 2 phases ----------------
__global__ __launch_bounds__(256) void k_stepq(int iter, int srcsel, int final_,
                                               const float* __restrict__ cb,
                                               const int* __restrict__ nsp,
                                               float* __restrict__ out)
{
    int ns = *nsp;
    const unsigned char* src = srcsel ? g_idxB : g_idxA;
    unsigned char* dst = srcsel ? g_idxA : g_idxB;
    int tx = threadIdx.x, ty = threadIdx.y, t = ty*32+tx;
    int X0 = blockIdx.x*128, Y0 = blockIdx.y*8, b = blockIdx.z;
    int gbase = (b << 16) + (Y0+ty)*256 + X0 + tx;
    if (iter > ns) {                        // uniform branch
#pragma unroll
        for (int p = 0; p < 4; p++) {
            unsigned char v = src[gbase + p*32];
            dst[gbase + p*32] = v;
            if (final_) out[gbase + p*32] = g_declut[v];
        }
        return;
    }

    __shared__ float sT[9*33*17];
    __shared__ float sA[32*17];
    __shared__ float sO[32*17];
    __shared__ float s_cb[512];
    __shared__ float s_cq[32];
    __shared__ float s_lut[32];
    __shared__ unsigned char sj[10*130];
    for (int i = t; i < 9*33*17; i += 256) sT[i] = g_T9[i];
    for (int i = t; i < 544; i += 256) { sA[i] = g_Acb[i]; sO[i] = g_OMB[i]; }
    for (int i = t; i < 512; i += 256) s_cb[i] = cb[i];
    if (t < 32) { s_cq[t] = g_cbsq[t]; s_lut[t] = g_declut[t]; }
    for (int i = t; i < 1300; i += 256) {
        int r = i/130, c = i%130;
        int gy = Y0+r-1, gx = X0+c-1;
        unsigned char v = 32;   // zero-code padding
        if ((unsigned)gy < 256u && (unsigned)gx < 256u)
            v = src[(b << 16) + gy*256 + gx];
        sj[i] = v;
    }
    __syncthreads();

#pragma unroll
    for (int P2 = 0; P2 < 2; P2++) {
        int off = P2*64;
        float zA[16], zB[16];
        {
            float accA[16], accB[16];
#pragma unroll
            for (int c = 0; c < 16; c++) { accA[c] = 0.f; accB[c] = 0.f; }
#pragma unroll
            for (int pos = 0; pos < 9; pos++) {
                int base = (ty + pos/3)*130 + tx + pos%3 + off;
                int jA = sj[base];
                int jB = sj[base + 32];
                const float* TA = &sT[(pos*33 + jA)*17];
                const float* TBp = &sT[(pos*33 + jB)*17];
#pragma unroll
                for (int c = 0; c < 16; c++) { accA[c] += TA[c]; accB[c] += TBp[c]; }
            }
            int cbase = (ty+1)*130 + tx+1 + off;
            int j0A = sj[cbase], j0B = sj[cbase + 32];
            const float* ArA = &sA[j0A*17];
            const float* OrA = &sO[j0A*17];
            const float* ArB = &sA[j0B*17];
            const float* OrB = &sO[j0B*17];
#pragma unroll
            for (int c = 0; c < 16; c++) {
                zA[c] = fmaf(OrA[c], fmaxf(accA[c], 0.f), ArA[c]);
                zB[c] = fmaf(OrB[c], fmaxf(accB[c], 0.f), ArB[c]);
            }
        }
        float bestA = 3.4e38f, bestB = 3.4e38f;
        int biA = 0, biB = 0;
#pragma unroll
        for (int k = 0; k < 32; k++) {
            const float4* c4 = (const float4*)&s_cb[k*16];
            float dotA = 0.f, dotB = 0.f;
#pragma unroll
            for (int g = 0; g < 4; g++) {
                float4 cv = c4[g];
                dotA = fmaf(cv.x, zA[g*4+0], dotA);
                dotA = fmaf(cv.y, zA[g*4+1], dotA);
                dotA = fmaf(cv.z, zA[g*4+2], dotA);
                dotA = fmaf(cv.w, zA[g*4+3], dotA);
                dotB = fmaf(cv.x, zB[g*4+0], dotB);
                dotB = fmaf(cv.y, zB[g*4+1], dotB);
                dotB = fmaf(cv.z, zB[g*4+2], dotB);
                dotB = fmaf(cv.w, zB[g*4+3], dotB);
            }
            float cq = s_cq[k];
            float dA = cq - 2.f*dotA;
            float dB = cq - 2.f*dotB;
            if (dA < bestA) { bestA = dA; biA = k; }
            if (dB < bestB) { bestB = dB; biB = k; }
        }
        dst[gbase + off]      = (unsigned char)biA;
        dst[gbase + off + 32] = (unsigned char)biB;
        if (final_) {
            out[gbase + off]      = s_lut[biA];
            out[gbase + off + 32] = s_lut[biB];
        }
    }
}

extern "C" void kernel_launch(void* const* d_in, const int* in_sizes, int n_in,
                              void* d_out, int out_size)
{
    const float* demo_in  = (const float*)d_in[0];
    const float* demo_out = (const float*)d_in[1];
    const float* test_in  = (const float*)d_in[2];
    const float* enc_w1   = (const float*)d_in[3];
    const float* enc_b1   = (const float*)d_in[4];
    const float* enc_w2   = (const float*)d_in[5];
    const float* enc_b2   = (const float*)d_in[6];
    const float* enc_lw   = (const float*)d_in[7];
    const float* enc_lb   = (const float*)d_in[8];
    const float* gu_w1    = (const float*)d_in[9];
    const float* gu_b1    = (const float*)d_in[10];
    const float* gu_w2    = (const float*)d_in[11];
    const float* gu_b2    = (const float*)d_in[12];
    const float* gt_w1    = (const float*)d_in[13];
    const float* gt_b1    = (const float*)d_in[14];
    const float* gt_w2    = (const float*)d_in[15];
    const float* gt_b2    = (const float*)d_in[16];
    const float* stem_w   = (const float*)d_in[17];
    const float* stem_b   = (const float*)d_in[18];
    const float* codebook = (const float*)d_in[19];
    const float* dec_w    = (const float*)d_in[20];
    const float* dec_b    = (const float*)d_in[21];
    const int*   n_steps  = (const int*)d_in[22];

    cudaFuncSetAttribute(k_step1f, cudaFuncAttributeMaxDynamicSharedMemorySize,
                         S1F_BYTES);

    k_enc1<<<128, 256>>>(demo_in, demo_out, enc_w1, enc_b1);
    k_enc2<<<dim3(16,8), dim3(32,8)>>>(enc_w2, enc_b2);
    k_small<<<1, 256>>>(enc_lw, enc_lb, gt_w1, gt_b1, gt_w2, gt_b2,
                        codebook, dec_w, dec_b);
    k_tables<<<16, 256>>>(gu_w1, gu_b1, gu_w2, gu_b2, codebook);
    k_step1f<<<dim3(8,32,TB), dim3(32,8), S1F_BYTES>>>(test_in, stem_w, stem_b, codebook);
    float* out = (float*)d_out;
    dim3 gridq(2, 32, TB), blk(32, 8);
    k_stepq<<<gridq, blk>>>(2, 0, 0, codebook, n_steps, out);
    k_stepq<<<gridq, blk>>>(3, 1, 0, codebook, n_steps, out);
    k_stepq<<<gridq, blk>>>(4, 0, 0, codebook, n_steps, out);
    k_stepq<<<gridq, blk>>>(5, 1, 1, codebook, n_steps, out);
}

// round 16
// speedup vs baseline: 3.4412x; 3.4412x over previous
#include <cuda_runtime.h>
#include <math.h>

#define TB 16
#define TS 256

// ---------------- device scratch ----------------
__device__ float g_h1[8*16*64*64];
__device__ float g_part[128*32];
__device__ float g_te[64];
__device__ float g_Wupd[2304];              // [co][ci][pos]
__device__ float g_Wtau[256];               // [co][ci]
__device__ float g_T9[9*33*17];             // [pos][code(33:32=zero)][c] stride-17
__device__ float g_Acb[32*17];              // beta*code
__device__ float g_OMB[32*17];              // 1-beta
__device__ float g_cbsq[32];
__device__ float g_declut[32];
__device__ unsigned char g_idxA[TB*TS*TS];
__device__ unsigned char g_idxB[TB*TS*TS];

// ---------------- encoder conv1 ----------------
__global__ __launch_bounds__(256) void k_enc1(const float* __restrict__ din,
                                              const float* __restrict__ dmo,
                                              const float* __restrict__ w1,
                                              const float* __restrict__ b1)
{
    __shared__ float sw[288];
    __shared__ float sb[16];
    int t = threadIdx.x;
    for (int i = t; i < 288; i += 256) sw[i] = w1[i];
    if (t < 16) sb[t] = b1[t];
    __syncthreads();
    int idx = blockIdx.x * 256 + t;
    int b = idx >> 12, p = idx & 4095, y = p >> 6, x = p & 63;
    const float* i0 = din + b * 4096;
    const float* i1 = dmo + b * 4096;
    float acc[16];
#pragma unroll
    for (int c = 0; c < 16; c++) acc[c] = sb[c];
#pragma unroll
    for (int ky = 0; ky < 3; ky++) {
        int yy = y + ky - 1;
        if ((unsigned)yy >= 64u) continue;
#pragma unroll
        for (int kx = 0; kx < 3; kx++) {
            int xx = x + kx - 1;
            if ((unsigned)xx >= 64u) continue;
            float v0 = i0[yy*64+xx], v1 = i1[yy*64+xx];
            int pos = ky*3+kx;
#pragma unroll
            for (int c = 0; c < 16; c++)
                acc[c] = fmaf(sw[c*18+pos], v0, fmaf(sw[c*18+9+pos], v1, acc[c]));
        }
    }
#pragma unroll
    for (int c = 0; c < 16; c++)
        g_h1[((b*16+c) << 12) + p] = fmaxf(acc[c], 0.f);
}

// ---------------- encoder conv2 + relu + spatial sum ----------------
__global__ __launch_bounds__(256) void k_enc2(const float* __restrict__ w2,
                                              const float* __restrict__ b2)
{
    __shared__ float sh[16][6][66];
    __shared__ float sw[32][145];
    __shared__ float spart[8][32];
    int tx = threadIdx.x, ty = threadIdx.y;
    int t = ty * 32 + tx;
    int band = blockIdx.x, b = blockIdx.y;
    float* swf = &sw[0][0];
    for (int i = t; i < 4608; i += 256) { int oc = i/144, j = i%144; swf[oc*145+j] = w2[i]; }
    int r0 = band * 4;
    for (int i = t; i < 16*6*66; i += 256) {
        int ci = i / 396; int rem = i % 396; int r = rem / 66; int xx = rem % 66;
        int gy = r0 + r - 1; int gx = xx - 1;
        float v = 0.f;
        if ((unsigned)gy < 64u && (unsigned)gx < 64u)
            v = g_h1[((b*16+ci) << 12) + gy*64 + gx];
        sh[ci][r][xx] = v;
    }
    __syncthreads();
    int oc = tx;
    float bias = b2[oc];
    float tsum = 0.f;
    for (int p = ty; p < 256; p += 8) {
        int r = p >> 6; int x = p & 63;
        float acc = bias;
#pragma unroll
        for (int ky = 0; ky < 3; ky++) {
#pragma unroll
            for (int kx = 0; kx < 3; kx++) {
                int pos = ky*3+kx;
#pragma unroll
                for (int ci = 0; ci < 16; ci++)
                    acc = fmaf(sh[ci][r+ky][x+kx], swf[oc*145 + ci*9 + pos], acc);
            }
        }
        tsum += fmaxf(acc, 0.f);
    }
    spart[ty][oc] = tsum;
    __syncthreads();
    if (ty == 0) {
        float s = 0.f;
#pragma unroll
        for (int k = 0; k < 8; k++) s += spart[k][oc];
        g_part[(b*16+band)*32 + oc] = s;
    }
}

// ---------------- slim tiny stage: te, tau hypernet, tau tables ----------------
__global__ __launch_bounds__(256) void k_small(
    const float* __restrict__ enc_lw, const float* __restrict__ enc_lb,
    const float* __restrict__ gt_w1, const float* __restrict__ gt_b1,
    const float* __restrict__ gt_w2, const float* __restrict__ gt_b2,
    const float* __restrict__ cb, const float* __restrict__ dec_w,
    const float* __restrict__ dec_b)
{
    __shared__ float s_hbar[32];
    __shared__ float s_te[64];
    __shared__ float s_ht[64];
    __shared__ float s_cb[512];
    int t = threadIdx.x;
    if (t < 32) {
        float s = 0.f;
        for (int i = 0; i < 128; i++) s += g_part[i*32 + t];
        s_hbar[t] = s * (1.f/(8.f*4096.f));
    }
    for (int i = t; i < 512; i += 256) s_cb[i] = cb[i];
    __syncthreads();
    if (t < 64) {
        float a = enc_lb[t];
        for (int f = 0; f < 32; f++) a = fmaf(enc_lw[t*32+f], s_hbar[f], a);
        s_te[t] = a;
        g_te[t] = a;
    }
    __syncthreads();
    if (t < 64) {
        float a = gt_b1[t];
        for (int e = 0; e < 64; e++) a = fmaf(gt_w1[t*64+e], s_te[e], a);
        s_ht[t] = fmaxf(a, 0.f);
    }
    __syncthreads();
    for (int o = t; o < 256; o += 256) {
        float a = gt_b2[o];
        for (int i = 0; i < 64; i++) a = fmaf(gt_w2[o*64+i], s_ht[i], a);
        g_Wtau[o] = a;
    }
    __syncthreads();
    for (int o = t; o < 512; o += 256) {
        int k = o >> 4, c = o & 15;
        float a = 0.f;
        for (int ci = 0; ci < 16; ci++) a = fmaf(g_Wtau[c*16+ci], s_cb[k*16+ci], a);
        float beta = 1.f / (1.f + __expf(-a));
        g_Acb[k*17+c] = beta * s_cb[k*16+c];
        g_OMB[k*17+c] = 1.f - beta;
    }
    if (t < 32) {
        float sq = 0.f, dv = dec_b[0];
        for (int c = 0; c < 16; c++) {
            float cc = s_cb[t*16+c];
            sq = fmaf(cc, cc, sq);
            dv = fmaf(dec_w[c], cc, dv);
        }
        g_cbsq[t] = sq;
        g_declut[t] = 1.f / (1.f + __expf(-dv));
    }
}

// ---------------- parallel table gen: one block per co ----------------
__global__ __launch_bounds__(256) void k_tables(
    const float* __restrict__ gu_w1, const float* __restrict__ gu_b1,
    const float* __restrict__ gu_w2, const float* __restrict__ gu_b2,
    const float* __restrict__ cb)
{
    __shared__ float s_hu[128];
    __shared__ float s_w[144];     // this co's Wupd slice [ci*9+pos]
    __shared__ float s_cb[512];
    int t = threadIdx.x;
    int co = blockIdx.x;
    for (int i = t; i < 512; i += 256) s_cb[i] = cb[i];
    if (t < 128) {
        float a = gu_b1[t];
        for (int e = 0; e < 64; e++) a = fmaf(gu_w1[t*64+e], g_te[e], a);
        s_hu[t] = fmaxf(a, 0.f);
    }
    __syncthreads();
    for (int i = t; i < 144; i += 256) {
        int o = co*144 + i;        // o = (co*16+ci)*9+pos, i = ci*9+pos
        float a = gu_b2[o];
        for (int j = 0; j < 128; j++) a = fmaf(gu_w2[o*128+j], s_hu[j], a);
        g_Wupd[o] = a;
        s_w[i] = a;
    }
    __syncthreads();
    for (int i = t; i < 297; i += 256) {
        int pos = i / 33, k = i % 33;
        float v = 0.f;
        if (k < 32) {
            for (int ci = 0; ci < 16; ci++)
                v = fmaf(s_w[ci*9+pos], s_cb[k*16+ci], v);
        }
        g_T9[(pos*33+k)*17 + co] = v;
    }
}

// ---------------- fused stem + step 1: co-split conv (4px x 4co per thread) ----------------
// dyn smem layout (float offsets):
//   s_t  float4[4*10*34] @0      (5440 floats)
//   sin_ [12*36]          @5440  (432)
//   s_sw [144]            @5872
//   s_sb [16]             @6016
//   s_W  [2304]           @6032  [pos][ci][co]
//   s_Wt [256]            @8336  [ci][co]
//   s_cb [512]            @8592
//   s_cq [32]             @9104
//   s_d  [256*20]         @9136  (5120) raw conv sums, stride-20 pad
#define S1F_FLOATS 14256
#define S1F_BYTES (S1F_FLOATS*4)

__global__ __launch_bounds__(256, 2) void k_step1f(const float* __restrict__ tin,
                                                   const float* __restrict__ stw,
                                                   const float* __restrict__ stb,
                                                   const float* __restrict__ cb)
{
    extern __shared__ float sm[];
    float4* s_t  = (float4*)sm;
    float*  sin_ = sm + 5440;
    float*  s_sw = sm + 5872;
    float*  s_sb = sm + 6016;
    float*  s_W  = sm + 6032;
    float*  s_Wt = sm + 8336;
    float*  s_cb = sm + 8592;
    float*  s_cq = sm + 9104;
    float*  s_d  = sm + 9136;

    int tx = threadIdx.x, ty = threadIdx.y, t = ty*32+tx;
    for (int i = t; i < 144; i += 256) { int co = i/9, pos = i%9; s_sw[pos*16+co] = stw[i]; }
    if (t < 16) s_sb[t] = stb[t];
    for (int i = t; i < 2304; i += 256) {
        int co = i & 15, ci = (i >> 4) & 15, pos = i >> 8;
        s_W[i] = g_Wupd[(co*16+ci)*9 + pos];
    }
    for (int i = t; i < 256; i += 256) { int co = i & 15, ci = i >> 4; s_Wt[i] = g_Wtau[co*16+ci]; }
    for (int i = t; i < 512; i += 256) s_cb[i] = cb[i];
    if (t < 32) s_cq[t] = g_cbsq[t];
    int X0 = blockIdx.x*32, Y0 = blockIdx.y*8, b = blockIdx.z;
    const float* img = tin + (size_t)b*65536;
    for (int i = t; i < 432; i += 256) {
        int rr = i/36, cc = i%36;
        int gy = Y0-2+rr, gx = X0-2+cc;
        float v = 0.f;
        if ((unsigned)gy < 256u && (unsigned)gx < 256u) v = img[gy*256+gx];
        sin_[i] = v;
    }
    __syncthreads();
    // stem over 10x34 halo region (zero outside image bounds)
    for (int i = t; i < 340; i += 256) {
        int r = i/34, c = i%34;
        int gy = Y0+r-1, gx = X0+c-1;
        float4 o0 = make_float4(0,0,0,0), o1 = o0, o2 = o0, o3 = o0;
        if ((unsigned)gy < 256u && (unsigned)gx < 256u) {
            float acc[16];
#pragma unroll
            for (int cc = 0; cc < 16; cc++) acc[cc] = s_sb[cc];
#pragma unroll
            for (int pos = 0; pos < 9; pos++) {
                float v = sin_[(r + pos/3)*36 + (c + pos%3)];
                const float4* w4 = (const float4*)&s_sw[pos*16];
#pragma unroll
                for (int g = 0; g < 4; g++) {
                    float4 wv = w4[g];
                    acc[g*4+0] = fmaf(wv.x, v, acc[g*4+0]);
                    acc[g*4+1] = fmaf(wv.y, v, acc[g*4+1]);
                    acc[g*4+2] = fmaf(wv.z, v, acc[g*4+2]);
                    acc[g*4+3] = fmaf(wv.w, v, acc[g*4+3]);
                }
            }
            o0 = make_float4(fmaxf(acc[0],0.f),fmaxf(acc[1],0.f),fmaxf(acc[2],0.f),fmaxf(acc[3],0.f));
            o1 = make_float4(fmaxf(acc[4],0.f),fmaxf(acc[5],0.f),fmaxf(acc[6],0.f),fmaxf(acc[7],0.f));
            o2 = make_float4(fmaxf(acc[8],0.f),fmaxf(acc[9],0.f),fmaxf(acc[10],0.f),fmaxf(acc[11],0.f));
            o3 = make_float4(fmaxf(acc[12],0.f),fmaxf(acc[13],0.f),fmaxf(acc[14],0.f),fmaxf(acc[15],0.f));
        }
        s_t[(0*10+r)*34+c] = o0;
        s_t[(1*10+r)*34+c] = o1;
        s_t[(2*10+r)*34+c] = o2;
        s_t[(3*10+r)*34+c] = o3;
    }
    __syncthreads();

    // co-split conv: thread = (slot, cog); slot -> x=slot&31, y0=slot>>5;
    {
        int slot = t >> 2, cog = t & 3;
        int cx = slot & 31, cy0 = slot >> 5;
        float4 acc0 = make_float4(0,0,0,0), acc1 = acc0, acc2 = acc0, acc3 = acc0;
#pragma unroll
        for (int pos = 0; pos < 9; pos++) {
            int dy = pos/3, dx = pos%3;
#pragma unroll
            for (int q = 0; q < 4; q++) {
                float4 v0 = s_t[(q*10 + cy0 + 0 + dy)*34 + cx + dx];
                float4 v1 = s_t[(q*10 + cy0 + 2 + dy)*34 + cx + dx];
                float4 v2 = s_t[(q*10 + cy0 + 4 + dy)*34 + cx + dx];
                float4 v3 = s_t[(q*10 + cy0 + 6 + dy)*34 + cx + dx];
                float c0[4] = {v0.x, v0.y, v0.z, v0.w};
                float c1[4] = {v1.x, v1.y, v1.z, v1.w};
                float c2[4] = {v2.x, v2.y, v2.z, v2.w};
                float c3[4] = {v3.x, v3.y, v3.z, v3.w};
#pragma unroll
                for (int u = 0; u < 4; u++) {
                    float4 w = *(const float4*)&s_W[(pos*16 + q*4 + u)*16 + cog*4];
                    float s0 = c0[u], s1 = c1[u], s2 = c2[u], s3 = c3[u];
                    acc0.x = fmaf(w.x, s0, acc0.x); acc0.y = fmaf(w.y, s0, acc0.y);
                    acc0.z = fmaf(w.z, s0, acc0.z); acc0.w = fmaf(w.w, s0, acc0.w);
                    acc1.x = fmaf(w.x, s1, acc1.x); acc1.y = fmaf(w.y, s1, acc1.y);
                    acc1.z = fmaf(w.z, s1, acc1.z); acc1.w = fmaf(w.w, s1, acc1.w);
                    acc2.x = fmaf(w.x, s2, acc2.x); acc2.y = fmaf(w.y, s2, acc2.y);
                    acc2.z = fmaf(w.z, s2, acc2.z); acc2.w = fmaf(w.w, s2, acc2.w);
                    acc3.x = fmaf(w.x, s3, acc3.x); acc3.y = fmaf(w.y, s3, acc3.y);
                    acc3.z = fmaf(w.z, s3, acc3.z); acc3.w = fmaf(w.w, s3, acc3.w);
                }
            }
        }
        *(float4*)&s_d[(slot +   0)*20 + cog*4] = acc0;
        *(float4*)&s_d[(slot +  64)*20 + cog*4] = acc1;
        *(float4*)&s_d[(slot + 128)*20 + cog*4] = acc2;
        *(float4*)&s_d[(slot + 192)*20 + cog*4] = acc3;
    }
    __syncthreads();

    // post-processing: 1 px per thread (px = t)
    {
        int x = t & 31, y = t >> 5;
        float acc[16];
#pragma unroll
        for (int g = 0; g < 4; g++) {
            float4 a = *(const float4*)&s_d[t*20 + g*4];
            acc[g*4+0] = a.x; acc[g*4+1] = a.y; acc[g*4+2] = a.z; acc[g*4+3] = a.w;
        }
        float zc[16];
#pragma unroll
        for (int q = 0; q < 4; q++) {
            float4 v = s_t[(q*10 + y+1)*34 + x+1];
            zc[q*4+0] = v.x; zc[q*4+1] = v.y; zc[q*4+2] = v.z; zc[q*4+3] = v.w;
        }
        float ta[16];
#pragma unroll
        for (int c = 0; c < 16; c++) ta[c] = 0.f;
#pragma unroll
        for (int ci = 0; ci < 16; ci++) {
            float s = zc[ci];
            const float4* w4 = (const float4*)&s_Wt[ci*16];
#pragma unroll
            for (int g = 0; g < 4; g++) {
                float4 wv = w4[g];
                ta[g*4+0] = fmaf(wv.x, s, ta[g*4+0]);
                ta[g*4+1] = fmaf(wv.y, s, ta[g*4+1]);
                ta[g*4+2] = fmaf(wv.z, s, ta[g*4+2]);
                ta[g*4+3] = fmaf(wv.w, s, ta[g*4+3]);
            }
        }
        float z[16];
#pragma unroll
        for (int c = 0; c < 16; c++) {
            float beta = 1.f / (1.f + __expf(-ta[c]));
            float delta = fmaxf(acc[c], 0.f);
            z[c] = fmaf(beta, zc[c] - delta, delta);
        }
        float best = 3.4e38f; int bi = 0;
#pragma unroll
        for (int k = 0; k < 32; k++) {
            const float4* c4 = (const float4*)&s_cb[k*16];
            float dot = 0.f;
#pragma unroll
            for (int g = 0; g < 4; g++) {
                float4 cv = c4[g];
                dot = fmaf(cv.x, z[g*4+0], dot);
                dot = fmaf(cv.y, z[g*4+1], dot);
                dot = fmaf(cv.z, z[g*4+2], dot);
                dot = fmaf(cv.w, z[g*4+3], dot);
            }
            float d = s_cq[k] - 2.f*dot;
            if (d < best) { best = d; bi = k; }
        }
        g_idxA[(b << 16) + (Y0+y)*256 + (X0+x)] = (unsigned char)bi;
    }
}

// ---------------- quantized step: 64x8 tile, 2 px/thread, phased joint VQ (R14-proven) ----------------
__global__ __launch_bounds__(256) void k_stepq(int iter, int srcsel, int final_,
                                               const float* __restrict__ cb,
                                               const int* __restrict__ nsp,
                                               float* __restrict__ out)
{
    int ns = *nsp;
    const unsigned char* src = srcsel ? g_idxB : g_idxA;
    unsigned char* dst = srcsel ? g_idxA : g_idxB;
    int tx = threadIdx.x, ty = threadIdx.y, t = ty*32+tx;
    int X0 = blockIdx.x*64, Y0 = blockIdx.y*8, b = blockIdx.z;
    int gbase = (b << 16) + (Y0+ty)*256 + X0 + tx;
    if (iter > ns) {                        // uniform branch
        unsigned char vA = src[gbase], vB = src[gbase+32];
        dst[gbase] = vA; dst[gbase+32] = vB;
        if (final_) { out[gbase] = g_declut[vA]; out[gbase+32] = g_declut[vB]; }
        return;
    }

    __shared__ float sT[9*33*17];
    __shared__ float sA[32*17];
    __shared__ float sO[32*17];
    __shared__ float s_cb[512];
    __shared__ float s_cq[32];
    __shared__ float s_lut[32];
    __shared__ unsigned char sj[10*66];
    for (int i = t; i < 9*33*17; i += 256) sT[i] = g_T9[i];
    for (int i = t; i < 544; i += 256) { sA[i] = g_Acb[i]; sO[i] = g_OMB[i]; }
    for (int i = t; i < 512; i += 256) s_cb[i] = cb[i];
    if (t < 32) { s_cq[t] = g_cbsq[t]; s_lut[t] = g_declut[t]; }
    for (int i = t; i < 660; i += 256) {
        int r = i/66, c = i%66;
        int gy = Y0+r-1, gx = X0+c-1;
        unsigned char v = 32;   // zero-code padding
        if ((unsigned)gy < 256u && (unsigned)gx < 256u)
            v = src[(b << 16) + gy*256 + gx];
        sj[i] = v;
    }
    __syncthreads();

    float zA[16], zB[16];
    {
        // phase 1: accumulate tables into zA/zB (accA/accB die here)
        float accA[16], accB[16];
#pragma unroll
        for (int c = 0; c < 16; c++) { accA[c] = 0.f; accB[c] = 0.f; }
#pragma unroll
        for (int pos = 0; pos < 9; pos++) {
            int base = (ty + pos/3)*66 + tx + pos%3;
            int jA = sj[base];
            int jB = sj[base + 32];
            const float* TA = &sT[(pos*33 + jA)*17];
            const float* TBp = &sT[(pos*33 + jB)*17];
#pragma unroll
            for (int c = 0; c < 16; c++) { accA[c] += TA[c]; accB[c] += TBp[c]; }
        }
        int cbase = (ty+1)*66 + tx+1;
        int j0A = sj[cbase], j0B = sj[cbase + 32];
        const float* ArA = &sA[j0A*17];
        const float* OrA = &sO[j0A*17];
        const float* ArB = &sA[j0B*17];
        const float* OrB = &sO[j0B*17];
#pragma unroll
        for (int c = 0; c < 16; c++) {
            zA[c] = fmaf(OrA[c], fmaxf(accA[c], 0.f), ArA[c]);
            zB[c] = fmaf(OrB[c], fmaxf(accB[c], 0.f), ArB[c]);
        }
    }

    // phase 2: joint VQ — each codebook float4 loaded ONCE for both pixels
    float bestA = 3.4e38f, bestB = 3.4e38f;
    int biA = 0, biB = 0;
#pragma unroll
    for (int k = 0; k < 32; k++) {
        const float4* c4 = (const float4*)&s_cb[k*16];
        float dotA = 0.f, dotB = 0.f;
#pragma unroll
        for (int g = 0; g < 4; g++) {
            float4 cv = c4[g];
            dotA = fmaf(cv.x, zA[g*4+0], dotA);
            dotA = fmaf(cv.y, zA[g*4+1], dotA);
            dotA = fmaf(cv.z, zA[g*4+2], dotA);
            dotA = fmaf(cv.w, zA[g*4+3], dotA);
            dotB = fmaf(cv.x, zB[g*4+0], dotB);
            dotB = fmaf(cv.y, zB[g*4+1], dotB);
            dotB = fmaf(cv.z, zB[g*4+2], dotB);
            dotB = fmaf(cv.w, zB[g*4+3], dotB);
        }
        float cq = s_cq[k];
        float dA = cq - 2.f*dotA;
        float dB = cq - 2.f*dotB;
        if (dA < bestA) { bestA = dA; biA = k; }
        if (dB < bestB) { bestB = dB; biB = k; }
    }

    dst[gbase]    = (unsigned char)biA;
    dst[gbase+32] = (unsigned char)biB;
    if (final_) {
        out[gbase]    = s_lut[biA];
        out[gbase+32] = s_lut[biB];
    }
}

extern "C" void kernel_launch(void* const* d_in, const int* in_sizes, int n_in,
                              void* d_out, int out_size)
{
    const float* demo_in  = (const float*)d_in[0];
    const float* demo_out = (const float*)d_in[1];
    const float* test_in  = (const float*)d_in[2];
    const float* enc_w1   = (const float*)d_in[3];
    const float* enc_b1   = (const float*)d_in[4];
    const float* enc_w2   = (const float*)d_in[5];
    const float* enc_b2   = (const float*)d_in[6];
    const float* enc_lw   = (const float*)d_in[7];
    const float* enc_lb   = (const float*)d_in[8];
    const float* gu_w1    = (const float*)d_in[9];
    const float* gu_b1    = (const float*)d_in[10];
    const float* gu_w2    = (const float*)d_in[11];
    const float* gu_b2    = (const float*)d_in[12];
    const float* gt_w1    = (const float*)d_in[13];
    const float* gt_b1    = (const float*)d_in[14];
    const float* gt_w2    = (const float*)d_in[15];
    const float* gt_b2    = (const float*)d_in[16];
    const float* stem_w   = (const float*)d_in[17];
    const float* stem_b   = (const float*)d_in[18];
    const float* codebook = (const float*)d_in[19];
    const float* dec_w    = (const float*)d_in[20];
    const float* dec_b    = (const float*)d_in[21];
    const int*   n_steps  = (const int*)d_in[22];

    cudaFuncSetAttribute(k_step1f, cudaFuncAttributeMaxDynamicSharedMemorySize,
                         S1F_BYTES);

    k_enc1<<<128, 256>>>(demo_in, demo_out, enc_w1, enc_b1);
    k_enc2<<<dim3(16,8), dim3(32,8)>>>(enc_w2, enc_b2);
    k_small<<<1, 256>>>(enc_lw, enc_lb, gt_w1, gt_b1, gt_w2, gt_b2,
                        codebook, dec_w, dec_b);
    k_tables<<<16, 256>>>(gu_w1, gu_b1, gu_w2, gu_b2, codebook);
    k_step1f<<<dim3(8,32,TB), dim3(32,8), S1F_BYTES>>>(test_in, stem_w, stem_b, codebook);
    float* out = (float*)d_out;
    dim3 gridq(4, 32, TB), blk(32, 8);
    k_stepq<<<gridq, blk>>>(2, 0, 0, codebook, n_steps, out);
    k_stepq<<<gridq, blk>>>(3, 1, 0, codebook, n_steps, out);
    k_stepq<<<gridq, blk>>>(4, 0, 0, codebook, n_steps, out);
    k_stepq<<<gridq, blk>>>(5, 1, 1, codebook, n_steps, out);
}